// round 5
// baseline (speedup 1.0000x reference)
#include <cuda_runtime.h>
#include <cuda_bf16.h>
#include <cstdint>
#include <cstddef>

// O3 tensor product, MUL=64, via mma.sync bf16 (hi/lo split, fp32 accum).
//   Q1 = s1 @ Wss ; Q2 = b @ Wvv ; P3 = s1 @ Wsv ; P4i = v1_i @ Wvs
//   out_s       = s2*Q1 + Q2 + bias
//   out_v[w][i] = P3[w]*v2_i + P4i[w]*s2
// (all reference scale factors cancel; b = dot(v1,v2)/sqrt(3))

#define THREADS 256
#define RPC 32                      // rows per chunk
#define MAT_BYTES (RPC * 128)       // one staged A matrix: 32 rows x 128B (64 bf16)
#define BUF_BYTES (10 * MAT_BYTES + 512)
#define SMEM_BYTES (2 * BUF_BYTES)

typedef unsigned int u32;

// 16B-block XOR swizzle offset for staged A: row r, 8-elem group ug
__device__ __forceinline__ u32 sw_off(int r, int ug) {
    return (u32)(r * 128 + ((ug ^ (r & 7)) << 4));
}

__device__ __forceinline__ u32 smem_u32(const void* p) {
    u32 a; asm("{ .reg .u64 t; cvta.to.shared.u64 t, %1; cvt.u32.u64 %0, t; }" : "=r"(a) : "l"(p));
    return a;
}

__device__ __forceinline__ void ldsm4(u32* d, u32 addr) {
    asm volatile("ldmatrix.sync.aligned.m8n8.x4.shared.b16 {%0,%1,%2,%3}, [%4];"
                 : "=r"(d[0]), "=r"(d[1]), "=r"(d[2]), "=r"(d[3]) : "r"(addr));
}

__device__ __forceinline__ void mma16816(float* c, const u32* a, const u32* b) {
    asm volatile("mma.sync.aligned.m16n8k16.row.col.f32.bf16.bf16.f32 "
                 "{%0,%1,%2,%3},{%4,%5,%6,%7},{%8,%9},{%0,%1,%2,%3};"
                 : "+f"(c[0]), "+f"(c[1]), "+f"(c[2]), "+f"(c[3])
                 : "r"(a[0]), "r"(a[1]), "r"(a[2]), "r"(a[3]), "r"(b[0]), "r"(b[1]));
}

// split two floats into packed bf16x2 hi and lo (lo = residual)
__device__ __forceinline__ void split2(float x0, float x1, u32& hi, u32& lo) {
    __nv_bfloat162 h = __floats2bfloat162_rn(x0, x1);
    float r0 = x0 - __bfloat162float(h.x);
    float r1 = x1 - __bfloat162float(h.y);
    __nv_bfloat162 l = __floats2bfloat162_rn(r0, r1);
    hi = *(u32*)&h; lo = *(u32*)&l;
}

// pack 8 floats -> hi uint4 + lo uint4 (bf16)
__device__ __forceinline__ void pack8(const float* x, uint4& hi, uint4& lo) {
    u32 h0,h1,h2,h3,l0,l1,l2,l3;
    split2(x[0], x[1], h0, l0);
    split2(x[2], x[3], h1, l1);
    split2(x[4], x[5], h2, l2);
    split2(x[6], x[7], h3, l3);
    hi = make_uint4(h0, h1, h2, h3);
    lo = make_uint4(l0, l1, l2, l3);
}

// A-matrix order in staging: 0 s1h 1 s1l 2 bh 3 bl 4 xh 5 xl 6 yh 7 yl 8 zh 9 zl
__device__ __forceinline__ void build_chunk(char* buf, const float* __restrict__ in1,
                                            const float* __restrict__ in2,
                                            int row0, int n, int t)
{
    const int r = t >> 3, ug = t & 7;
    int row = row0 + r; if (row >= n) row = n - 1;
    const float4* p1 = (const float4*)(in1 + (size_t)row * 256);

    const float4 q = *(const float4*)(in2 + (size_t)row * 4);   // s2, v2x, v2y, v2z
    if (ug == 0) *(float4*)(buf + 10 * MAT_BYTES + r * 16) = q;

    const float4 s1a = p1[2 * ug], s1b = p1[2 * ug + 1];
    float4 v[6];
#pragma unroll
    for (int i = 0; i < 6; i++) v[i] = p1[16 + 6 * ug + i];
    const float* vv = (const float*)v;            // 24 floats: v1[u][xyz], u = 8ug..8ug+7

    const float s1[8] = { s1a.x, s1a.y, s1a.z, s1a.w, s1b.x, s1b.y, s1b.z, s1b.w };
    const float INV_SQRT3 = 0.57735026918962576451f;
    float bb[8], vx[8], vy[8], vz[8];
#pragma unroll
    for (int j = 0; j < 8; j++) {
        vx[j] = vv[3 * j]; vy[j] = vv[3 * j + 1]; vz[j] = vv[3 * j + 2];
        bb[j] = (vx[j] * q.y + vy[j] * q.z + vz[j] * q.w) * INV_SQRT3;
    }

    const u32 off = sw_off(r, ug);
    uint4 hi, lo;
    pack8(s1, hi, lo);
    *(uint4*)(buf + 0 * MAT_BYTES + off) = hi; *(uint4*)(buf + 1 * MAT_BYTES + off) = lo;
    pack8(bb, hi, lo);
    *(uint4*)(buf + 2 * MAT_BYTES + off) = hi; *(uint4*)(buf + 3 * MAT_BYTES + off) = lo;
    pack8(vx, hi, lo);
    *(uint4*)(buf + 4 * MAT_BYTES + off) = hi; *(uint4*)(buf + 5 * MAT_BYTES + off) = lo;
    pack8(vy, hi, lo);
    *(uint4*)(buf + 6 * MAT_BYTES + off) = hi; *(uint4*)(buf + 7 * MAT_BYTES + off) = lo;
    pack8(vz, hi, lo);
    *(uint4*)(buf + 8 * MAT_BYTES + off) = hi; *(uint4*)(buf + 9 * MAT_BYTES + off) = lo;
}

__global__ void __launch_bounds__(THREADS, 1)
o3tp_mma_kernel(const float* __restrict__ in1, const float* __restrict__ in2,
                const float* __restrict__ Wss, const float* __restrict__ Wvv,
                const float* __restrict__ Wsv, const float* __restrict__ Wvs,
                const float* __restrict__ bias, float* __restrict__ out, int n)
{
    extern __shared__ char smem[];
    const u32 sbase = smem_u32(smem);
    const int t = threadIdx.x, wid = t >> 5, lane = t & 31;

    // ---- persistent B fragments: warp's n-slice (8 cols) of all 4 matrices ----
    u32 Bh[4][4][2], Bl[4][4][2];
    {
        const int wcol = wid * 8 + (lane >> 2);
        const float* Ws[4] = { Wss, Wvv, Wsv, Wvs };
#pragma unroll
        for (int m = 0; m < 4; m++)
#pragma unroll
            for (int kt = 0; kt < 4; kt++)
#pragma unroll
                for (int b2 = 0; b2 < 2; b2++) {
                    const int u = kt * 16 + (lane & 3) * 2 + b2 * 8;
                    const float w0 = __ldg(Ws[m] + u * 64 + wcol);
                    const float w1 = __ldg(Ws[m] + (u + 1) * 64 + wcol);
                    split2(w0, w1, Bh[m][kt][b2], Bl[m][kt][b2]);
                }
    }
    float2 bias2;
    {
        const int w0 = wid * 8 + (lane & 3) * 2;
        bias2 = make_float2(__ldg(bias + w0), __ldg(bias + w0 + 1));
    }

    const int nch = (n + RPC - 1) / RPC;
    int c = blockIdx.x;
    if (c < nch) build_chunk(smem, in1, in2, c * RPC, n, t);
    __syncthreads();

    int p = 0;
    for (; c < nch; c += gridDim.x) {
        const int cn = c + gridDim.x;
        if (cn < nch) build_chunk(smem + (p ^ 1) * BUF_BYTES, in1, in2, cn * RPC, n, t);

        // ---- MMA phase on buffer p ----
        float acc[6][2][4];
#pragma unroll
        for (int g = 0; g < 6; g++)
#pragma unroll
            for (int mt = 0; mt < 2; mt++)
#pragma unroll
                for (int k = 0; k < 4; k++) acc[g][mt][k] = 0.0f;

        const u32 abase = sbase + (u32)(p * BUF_BYTES);
        const int rl = (lane & 15);
        const int rlo = rl & 7;
#pragma unroll
        for (int kt = 0; kt < 4; kt++) {
#pragma unroll
            for (int mt = 0; mt < 2; mt++) {
                const int rr = mt * 16 + rl;
                const int cb = (kt * 2 + (lane >> 4)) ^ rlo;
                const u32 aoff = abase + (u32)(rr * 128 + cb * 16);
                u32 ah[4], al[4];
                // s1 -> Wss (acc0) and Wsv (acc2)
                ldsm4(ah, aoff + 0 * MAT_BYTES);
                ldsm4(al, aoff + 1 * MAT_BYTES);
                mma16816(acc[0][mt], ah, Bh[0][kt]);
                mma16816(acc[0][mt], al, Bh[0][kt]);
                mma16816(acc[0][mt], ah, Bl[0][kt]);
                mma16816(acc[2][mt], ah, Bh[2][kt]);
                mma16816(acc[2][mt], al, Bh[2][kt]);
                mma16816(acc[2][mt], ah, Bl[2][kt]);
                // b -> Wvv (acc1)
                ldsm4(ah, aoff + 2 * MAT_BYTES);
                ldsm4(al, aoff + 3 * MAT_BYTES);
                mma16816(acc[1][mt], ah, Bh[1][kt]);
                mma16816(acc[1][mt], al, Bh[1][kt]);
                mma16816(acc[1][mt], ah, Bl[1][kt]);
                // vx,vy,vz -> Wvs (acc3..5)
#pragma unroll
                for (int i = 0; i < 3; i++) {
                    ldsm4(ah, aoff + (4 + 2 * i) * MAT_BYTES);
                    ldsm4(al, aoff + (5 + 2 * i) * MAT_BYTES);
                    mma16816(acc[3 + i][mt], ah, Bh[3][kt]);
                    mma16816(acc[3 + i][mt], al, Bh[3][kt]);
                    mma16816(acc[3 + i][mt], ah, Bl[3][kt]);
                }
            }
        }

        // ---- epilogue ----
        const float4* sin2 = (const float4*)(smem + p * BUF_BYTES + 10 * MAT_BYTES);
        const int row0 = c * RPC;
        const int wc = wid * 8 + (lane & 3) * 2;
#pragma unroll
        for (int mt = 0; mt < 2; mt++) {
#pragma unroll
            for (int h = 0; h < 2; h++) {
                const int rloc = (lane >> 2) + h * 8 + mt * 16;
                const int row = row0 + rloc;
                if (row >= n) continue;
                const float4 q = sin2[rloc];
                float* o = out + (size_t)row * 256;
                const int ci = h * 2;
                const float s0 = q.x * acc[0][mt][ci]     + acc[1][mt][ci]     + bias2.x;
                const float s1v = q.x * acc[0][mt][ci + 1] + acc[1][mt][ci + 1] + bias2.y;
                *(float2*)(o + wc) = make_float2(s0, s1v);

                float vv6[6];
#pragma unroll
                for (int j = 0; j < 2; j++) {
                    const float p3 = acc[2][mt][ci + j];
                    vv6[3 * j]     = p3 * q.y + acc[3][mt][ci + j] * q.x;
                    vv6[3 * j + 1] = p3 * q.z + acc[4][mt][ci + j] * q.x;
                    vv6[3 * j + 2] = p3 * q.w + acc[5][mt][ci + j] * q.x;
                }
                float* ov = o + 64 + 3 * wc;
                *(float2*)(ov)     = make_float2(vv6[0], vv6[1]);
                *(float2*)(ov + 2) = make_float2(vv6[2], vv6[3]);
                *(float2*)(ov + 4) = make_float2(vv6[4], vv6[5]);
            }
        }
        __syncthreads();
        p ^= 1;
    }
}

extern "C" void kernel_launch(void* const* d_in, const int* in_sizes, int n_in,
                              void* d_out, int out_size)
{
    const float* in1  = (const float*)d_in[0];
    const float* in2  = (const float*)d_in[1];
    const float* Wss  = (const float*)d_in[2];
    const float* Wvv  = (const float*)d_in[3];
    const float* Wsv  = (const float*)d_in[4];
    const float* Wvs  = (const float*)d_in[5];
    const float* bias = (const float*)d_in[6];
    float* out = (float*)d_out;

    const int n = in_sizes[0] / 256;

    cudaFuncSetAttribute(o3tp_mma_kernel, cudaFuncAttributeMaxDynamicSharedMemorySize, SMEM_BYTES);

    int dev = 0, sms = 148;
    cudaGetDevice(&dev);
    cudaDeviceGetAttribute(&sms, cudaDevAttrMultiProcessorCount, dev);

    o3tp_mma_kernel<<<2 * sms, THREADS, SMEM_BYTES>>>(in1, in2, Wss, Wvv, Wsv, Wvs, bias, out, n);
}

// round 6
// speedup vs baseline: 1.0184x; 1.0184x over previous
#include <cuda_runtime.h>
#include <cuda_bf16.h>
#include <cstdint>
#include <cstddef>

// O3 tensor product, MUL=64, via mma.sync bf16 (hi/lo split, fp32 accum).
//   Q1 = s1 @ Wss ; Q2 = b @ Wvv ; P3 = s1 @ Wsv ; P4i = v1_i @ Wvs
//   out_s       = s2*Q1 + Q2 + bias
//   out_v[w][i] = P3[w]*v2_i + P4i[w]*s2
// (all reference scale factors cancel; b = dot(v1,v2)/sqrt(3))

#define THREADS 512
#define RPC 32                      // rows per chunk
#define MAT_BYTES (RPC * 128)       // one staged A matrix: 32 rows x 128B (64 bf16)
#define BUF_BYTES (10 * MAT_BYTES + 512)
#define SMEM_BYTES (2 * BUF_BYTES)

typedef unsigned int u32;

__device__ __forceinline__ u32 smem_u32(const void* p) {
    u32 a; asm("{ .reg .u64 t; cvta.to.shared.u64 t, %1; cvt.u32.u64 %0, t; }" : "=r"(a) : "l"(p));
    return a;
}

__device__ __forceinline__ void ldsm4(u32* d, u32 addr) {
    asm volatile("ldmatrix.sync.aligned.m8n8.x4.shared.b16 {%0,%1,%2,%3}, [%4];"
                 : "=r"(d[0]), "=r"(d[1]), "=r"(d[2]), "=r"(d[3]) : "r"(addr));
}

__device__ __forceinline__ void mma16816(float* c, const u32* a, const u32* b) {
    asm volatile("mma.sync.aligned.m16n8k16.row.col.f32.bf16.bf16.f32 "
                 "{%0,%1,%2,%3},{%4,%5,%6,%7},{%8,%9},{%0,%1,%2,%3};"
                 : "+f"(c[0]), "+f"(c[1]), "+f"(c[2]), "+f"(c[3])
                 : "r"(a[0]), "r"(a[1]), "r"(a[2]), "r"(a[3]), "r"(b[0]), "r"(b[1]));
}

// split two floats into packed bf16x2 hi and lo (lo = residual)
__device__ __forceinline__ void split2(float x0, float x1, u32& hi, u32& lo) {
    __nv_bfloat162 h = __floats2bfloat162_rn(x0, x1);
    float r0 = x0 - __bfloat162float(h.x);
    float r1 = x1 - __bfloat162float(h.y);
    __nv_bfloat162 l = __floats2bfloat162_rn(r0, r1);
    hi = *(u32*)&h; lo = *(u32*)&l;
}

// pack 4 floats -> hi uint2 + lo uint2 (bf16)
__device__ __forceinline__ void pack4(const float* x, uint2& hi, uint2& lo) {
    u32 h0, h1, l0, l1;
    split2(x[0], x[1], h0, l0);
    split2(x[2], x[3], h1, l1);
    hi = make_uint2(h0, h1);
    lo = make_uint2(l0, l1);
}

// A-matrix order in staging: 0 s1h 1 s1l 2 bh 3 bl 4 xh 5 xl 6 yh 7 yl 8 zh 9 zl
// Work item per thread: r = t>>4 (row 0..31), g4 = t&15 (u-group of 4: u=4g4..4g4+3)
__device__ __forceinline__ void build_chunk(char* buf, const float* __restrict__ in1,
                                            const float* __restrict__ in2,
                                            int row0, int n, int t)
{
    const int r = t >> 4, g4 = t & 15;
    int row = row0 + r; if (row >= n) row = n - 1;
    const float4* p1 = (const float4*)(in1 + (size_t)row * 256);

    if (g4 == 0) {
        const float4 q = *(const float4*)(in2 + (size_t)row * 4);   // s2, v2x, v2y, v2z
        *(float4*)(buf + 10 * MAT_BYTES + r * 16) = q;
    }
    const float4 qv = *(const float4*)(in2 + (size_t)row * 4);

    const float4 s1a = p1[g4];                 // s1[u], u = 4g4..4g4+3
    float4 v[3];
#pragma unroll
    for (int i = 0; i < 3; i++) v[i] = p1[16 + 3 * g4 + i];
    const float* vv = (const float*)v;         // 12 floats: v1[u][xyz]

    const float s1[4] = { s1a.x, s1a.y, s1a.z, s1a.w };
    const float INV_SQRT3 = 0.57735026918962576451f;
    float bb[4], vx[4], vy[4], vz[4];
#pragma unroll
    for (int j = 0; j < 4; j++) {
        vx[j] = vv[3 * j]; vy[j] = vv[3 * j + 1]; vz[j] = vv[3 * j + 2];
        bb[j] = (vx[j] * qv.y + vy[j] * qv.z + vz[j] * qv.w) * INV_SQRT3;
    }

    // swizzled 8B offset: 16B block = g4>>1, XOR with row&7, sub-8B = g4&1
    const u32 off = (u32)(r * 128 + (((g4 >> 1) ^ (r & 7)) << 4) + (g4 & 1) * 8);
    uint2 hi, lo;
    pack4(s1, hi, lo);
    *(uint2*)(buf + 0 * MAT_BYTES + off) = hi; *(uint2*)(buf + 1 * MAT_BYTES + off) = lo;
    pack4(bb, hi, lo);
    *(uint2*)(buf + 2 * MAT_BYTES + off) = hi; *(uint2*)(buf + 3 * MAT_BYTES + off) = lo;
    pack4(vx, hi, lo);
    *(uint2*)(buf + 4 * MAT_BYTES + off) = hi; *(uint2*)(buf + 5 * MAT_BYTES + off) = lo;
    pack4(vy, hi, lo);
    *(uint2*)(buf + 6 * MAT_BYTES + off) = hi; *(uint2*)(buf + 7 * MAT_BYTES + off) = lo;
    pack4(vz, hi, lo);
    *(uint2*)(buf + 8 * MAT_BYTES + off) = hi; *(uint2*)(buf + 9 * MAT_BYTES + off) = lo;
}

__global__ void __launch_bounds__(THREADS, 1)
o3tp_mma_kernel(const float* __restrict__ in1, const float* __restrict__ in2,
                const float* __restrict__ Wss, const float* __restrict__ Wvv,
                const float* __restrict__ Wsv, const float* __restrict__ Wvs,
                const float* __restrict__ bias, float* __restrict__ out, int n)
{
    extern __shared__ char smem[];
    const u32 sbase = smem_u32(smem);
    const int t = threadIdx.x, wid = t >> 5, lane = t & 31;
    const int nw = wid & 7;         // n-slice: cols nw*8..nw*8+7
    const int mt = wid >> 3;        // m-half: rows mt*16..mt*16+15

    // ---- persistent B fragments: warp's n-slice (8 cols) of all 4 matrices ----
    u32 Bh[4][4][2], Bl[4][4][2];
    {
        const int wcol = nw * 8 + (lane >> 2);
        const float* Ws[4] = { Wss, Wvv, Wsv, Wvs };
#pragma unroll
        for (int m = 0; m < 4; m++)
#pragma unroll
            for (int kt = 0; kt < 4; kt++)
#pragma unroll
                for (int b2 = 0; b2 < 2; b2++) {
                    const int u = kt * 16 + (lane & 3) * 2 + b2 * 8;
                    const float w0 = __ldg(Ws[m] + u * 64 + wcol);
                    const float w1 = __ldg(Ws[m] + (u + 1) * 64 + wcol);
                    split2(w0, w1, Bh[m][kt][b2], Bl[m][kt][b2]);
                }
    }
    float2 bias2;
    {
        const int w0 = nw * 8 + (lane & 3) * 2;
        bias2 = make_float2(__ldg(bias + w0), __ldg(bias + w0 + 1));
    }

    const int nch = (n + RPC - 1) / RPC;
    int c = blockIdx.x;
    if (c < nch) build_chunk(smem, in1, in2, c * RPC, n, t);
    __syncthreads();

    int p = 0;
    for (; c < nch; c += gridDim.x) {
        const int cn = c + gridDim.x;
        if (cn < nch) build_chunk(smem + (p ^ 1) * BUF_BYTES, in1, in2, cn * RPC, n, t);

        // ---- MMA phase on buffer p: warp computes M=16 (m-half mt), N=8 (nw) ----
        float acc[6][4];
#pragma unroll
        for (int g = 0; g < 6; g++)
#pragma unroll
            for (int k = 0; k < 4; k++) acc[g][k] = 0.0f;

        const u32 abase = sbase + (u32)(p * BUF_BYTES);
        const int rl = lane & 15;
        const int rlo = rl & 7;
        const int rr = mt * 16 + rl;
#pragma unroll
        for (int kt = 0; kt < 4; kt++) {
            const int cb = (kt * 2 + (lane >> 4)) ^ rlo;
            const u32 aoff = abase + (u32)(rr * 128 + cb * 16);
            u32 ah[4], al[4];
            // s1 -> Wss (acc0) and Wsv (acc2)
            ldsm4(ah, aoff + 0 * MAT_BYTES);
            ldsm4(al, aoff + 1 * MAT_BYTES);
            mma16816(acc[0], ah, Bh[0][kt]);
            mma16816(acc[0], al, Bh[0][kt]);
            mma16816(acc[0], ah, Bl[0][kt]);
            mma16816(acc[2], ah, Bh[2][kt]);
            mma16816(acc[2], al, Bh[2][kt]);
            mma16816(acc[2], ah, Bl[2][kt]);
            // b -> Wvv (acc1)
            ldsm4(ah, aoff + 2 * MAT_BYTES);
            ldsm4(al, aoff + 3 * MAT_BYTES);
            mma16816(acc[1], ah, Bh[1][kt]);
            mma16816(acc[1], al, Bh[1][kt]);
            mma16816(acc[1], ah, Bl[1][kt]);
            // vx,vy,vz -> Wvs (acc3..5)
#pragma unroll
            for (int i = 0; i < 3; i++) {
                ldsm4(ah, aoff + (4 + 2 * i) * MAT_BYTES);
                ldsm4(al, aoff + (5 + 2 * i) * MAT_BYTES);
                mma16816(acc[3 + i], ah, Bh[3][kt]);
                mma16816(acc[3 + i], al, Bh[3][kt]);
                mma16816(acc[3 + i], ah, Bl[3][kt]);
            }
        }

        // ---- epilogue ----
        const float4* sin2 = (const float4*)(smem + p * BUF_BYTES + 10 * MAT_BYTES);
        const int row0 = c * RPC;
        const int wc = nw * 8 + (lane & 3) * 2;
#pragma unroll
        for (int h = 0; h < 2; h++) {
            const int rloc = mt * 16 + (lane >> 2) + h * 8;
            const int row = row0 + rloc;
            if (row >= n) continue;
            const float4 q = sin2[rloc];
            float* o = out + (size_t)row * 256;
            const int ci = h * 2;
            const float s0  = q.x * acc[0][ci]     + acc[1][ci]     + bias2.x;
            const float s1v = q.x * acc[0][ci + 1] + acc[1][ci + 1] + bias2.y;
            *(float2*)(o + wc) = make_float2(s0, s1v);

            float vv6[6];
#pragma unroll
            for (int j = 0; j < 2; j++) {
                const float p3 = acc[2][ci + j];
                vv6[3 * j]     = p3 * q.y + acc[3][ci + j] * q.x;
                vv6[3 * j + 1] = p3 * q.z + acc[4][ci + j] * q.x;
                vv6[3 * j + 2] = p3 * q.w + acc[5][ci + j] * q.x;
            }
            float* ov = o + 64 + 3 * wc;
            *(float2*)(ov)     = make_float2(vv6[0], vv6[1]);
            *(float2*)(ov + 2) = make_float2(vv6[2], vv6[3]);
            *(float2*)(ov + 4) = make_float2(vv6[4], vv6[5]);
        }
        __syncthreads();
        p ^= 1;
    }
}

extern "C" void kernel_launch(void* const* d_in, const int* in_sizes, int n_in,
                              void* d_out, int out_size)
{
    const float* in1  = (const float*)d_in[0];
    const float* in2  = (const float*)d_in[1];
    const float* Wss  = (const float*)d_in[2];
    const float* Wvv  = (const float*)d_in[3];
    const float* Wsv  = (const float*)d_in[4];
    const float* Wvs  = (const float*)d_in[5];
    const float* bias = (const float*)d_in[6];
    float* out = (float*)d_out;

    const int n = in_sizes[0] / 256;

    cudaFuncSetAttribute(o3tp_mma_kernel, cudaFuncAttributeMaxDynamicSharedMemorySize, SMEM_BYTES);

    int dev = 0, sms = 148;
    cudaGetDevice(&dev);
    cudaDeviceGetAttribute(&sms, cudaDevAttrMultiProcessorCount, dev);

    o3tp_mma_kernel<<<sms, THREADS, SMEM_BYTES>>>(in1, in2, Wss, Wvv, Wsv, Wvs, bias, out, n);
}

// round 7
// speedup vs baseline: 1.0262x; 1.0077x over previous
#include <cuda_runtime.h>
#include <cuda_bf16.h>
#include <cstdint>
#include <cstddef>

// O3 tensor product, MUL=64, via mma.sync bf16 (hi/lo split, fp32 accum).
//   Q1 = s1 @ Wss ; Q2 = b @ Wvv ; P3 = s1 @ Wsv ; P4i = v1_i @ Wvs
//   out_s       = s2*Q1 + Q2 + bias
//   out_v[w][i] = P3[w]*v2_i + P4i[w]*s2
// (all reference scale factors cancel; b = dot(v1,v2)/sqrt(3))

#define THREADS 512
#define RPC 32                      // rows per chunk
#define MAT_BYTES (RPC * 128)       // one staged A matrix: 32 rows x 128B (64 bf16)
#define BUF_BYTES (10 * MAT_BYTES + 512)
#define SMEM_BYTES (2 * BUF_BYTES)

typedef unsigned int u32;

__device__ __forceinline__ u32 smem_u32(const void* p) {
    u32 a; asm("{ .reg .u64 t; cvta.to.shared.u64 t, %1; cvt.u32.u64 %0, t; }" : "=r"(a) : "l"(p));
    return a;
}

__device__ __forceinline__ void ldsm4(u32* d, u32 addr) {
    asm volatile("ldmatrix.sync.aligned.m8n8.x4.shared.b16 {%0,%1,%2,%3}, [%4];"
                 : "=r"(d[0]), "=r"(d[1]), "=r"(d[2]), "=r"(d[3]) : "r"(addr));
}

__device__ __forceinline__ void mma16816(float* c, const u32* a, const u32* b) {
    asm volatile("mma.sync.aligned.m16n8k16.row.col.f32.bf16.bf16.f32 "
                 "{%0,%1,%2,%3},{%4,%5,%6,%7},{%8,%9},{%0,%1,%2,%3};"
                 : "+f"(c[0]), "+f"(c[1]), "+f"(c[2]), "+f"(c[3])
                 : "r"(a[0]), "r"(a[1]), "r"(a[2]), "r"(a[3]), "r"(b[0]), "r"(b[1]));
}

// split two floats into packed bf16x2 hi and lo (lo = residual)
__device__ __forceinline__ void split2(float x0, float x1, u32& hi, u32& lo) {
    __nv_bfloat162 h = __floats2bfloat162_rn(x0, x1);
    float r0 = x0 - __bfloat162float(h.x);
    float r1 = x1 - __bfloat162float(h.y);
    __nv_bfloat162 l = __floats2bfloat162_rn(r0, r1);
    hi = *(u32*)&h; lo = *(u32*)&l;
}

// pack 4 floats -> hi uint2 + lo uint2 (bf16)
__device__ __forceinline__ void pack4(const float* x, uint2& hi, uint2& lo) {
    u32 h0, h1, l0, l1;
    split2(x[0], x[1], h0, l0);
    split2(x[2], x[3], h1, l1);
    hi = make_uint2(h0, h1);
    lo = make_uint2(l0, l1);
}

// A-matrix order in staging: 0 s1h 1 s1l 2 bh 3 bl 4 xh 5 xl 6 yh 7 yl 8 zh 9 zl
// Work item per thread: r = t>>4 (row 0..31), g4 = t&15 (u-group of 4: u=4g4..4g4+3)
__device__ __forceinline__ void build_chunk(char* buf, const float* __restrict__ in1,
                                            const float* __restrict__ in2,
                                            int row0, int n, int t)
{
    const int r = t >> 4, g4 = t & 15;
    int row = row0 + r; if (row >= n) row = n - 1;
    const float4* p1 = (const float4*)(in1 + (size_t)row * 256);

    if (g4 == 0) {
        const float4 q = *(const float4*)(in2 + (size_t)row * 4);   // s2, v2x, v2y, v2z
        *(float4*)(buf + 10 * MAT_BYTES + r * 16) = q;
    }
    const float4 qv = *(const float4*)(in2 + (size_t)row * 4);

    const float4 s1a = p1[g4];                 // s1[u], u = 4g4..4g4+3
    float4 v[3];
#pragma unroll
    for (int i = 0; i < 3; i++) v[i] = p1[16 + 3 * g4 + i];
    const float* vv = (const float*)v;         // 12 floats: v1[u][xyz]

    const float s1[4] = { s1a.x, s1a.y, s1a.z, s1a.w };
    const float INV_SQRT3 = 0.57735026918962576451f;
    float bb[4], vx[4], vy[4], vz[4];
#pragma unroll
    for (int j = 0; j < 4; j++) {
        vx[j] = vv[3 * j]; vy[j] = vv[3 * j + 1]; vz[j] = vv[3 * j + 2];
        bb[j] = (vx[j] * qv.y + vy[j] * qv.z + vz[j] * qv.w) * INV_SQRT3;
    }

    // swizzled 8B offset: 16B block = g4>>1, XOR with row&7, sub-8B = g4&1
    const u32 off = (u32)(r * 128 + (((g4 >> 1) ^ (r & 7)) << 4) + (g4 & 1) * 8);
    uint2 hi, lo;
    pack4(s1, hi, lo);
    *(uint2*)(buf + 0 * MAT_BYTES + off) = hi; *(uint2*)(buf + 1 * MAT_BYTES + off) = lo;
    pack4(bb, hi, lo);
    *(uint2*)(buf + 2 * MAT_BYTES + off) = hi; *(uint2*)(buf + 3 * MAT_BYTES + off) = lo;
    pack4(vx, hi, lo);
    *(uint2*)(buf + 4 * MAT_BYTES + off) = hi; *(uint2*)(buf + 5 * MAT_BYTES + off) = lo;
    pack4(vy, hi, lo);
    *(uint2*)(buf + 6 * MAT_BYTES + off) = hi; *(uint2*)(buf + 7 * MAT_BYTES + off) = lo;
    pack4(vz, hi, lo);
    *(uint2*)(buf + 8 * MAT_BYTES + off) = hi; *(uint2*)(buf + 9 * MAT_BYTES + off) = lo;
}

__global__ void __launch_bounds__(THREADS, 1)
o3tp_mma_kernel(const float* __restrict__ in1, const float* __restrict__ in2,
                const float* __restrict__ Wss, const float* __restrict__ Wvv,
                const float* __restrict__ Wsv, const float* __restrict__ Wvs,
                const float* __restrict__ bias, float* __restrict__ out, int n)
{
    extern __shared__ char smem[];
    const u32 sbase = smem_u32(smem);
    const int t = threadIdx.x, wid = t >> 5, lane = t & 31;
    const int nw = wid & 7;         // n-slice: cols nw*8..nw*8+7
    const int mt = wid >> 3;        // m-half: rows mt*16..mt*16+15

    // ---- persistent B fragments: warp's n-slice (8 cols) of all 4 matrices ----
    u32 Bh[4][4][2], Bl[4][4][2];
    {
        const int wcol = nw * 8 + (lane >> 2);
        const float* Ws[4] = { Wss, Wvv, Wsv, Wvs };
#pragma unroll
        for (int m = 0; m < 4; m++)
#pragma unroll
            for (int kt = 0; kt < 4; kt++)
#pragma unroll
                for (int b2 = 0; b2 < 2; b2++) {
                    const int u = kt * 16 + (lane & 3) * 2 + b2 * 8;
                    const float w0 = __ldg(Ws[m] + u * 64 + wcol);
                    const float w1 = __ldg(Ws[m] + (u + 1) * 64 + wcol);
                    split2(w0, w1, Bh[m][kt][b2], Bl[m][kt][b2]);
                }
    }
    float2 bias2;
    {
        const int w0 = nw * 8 + (lane & 3) * 2;
        bias2 = make_float2(__ldg(bias + w0), __ldg(bias + w0 + 1));
    }

    const int nch = (n + RPC - 1) / RPC;
    int c = blockIdx.x;
    if (c < nch) build_chunk(smem, in1, in2, c * RPC, n, t);
    __syncthreads();

    int p = 0;
    for (; c < nch; c += gridDim.x) {
        const int cn = c + gridDim.x;
        if (cn < nch) build_chunk(smem + (p ^ 1) * BUF_BYTES, in1, in2, cn * RPC, n, t);

        // ---- MMA phase on buffer p: warp computes M=16 (m-half mt), N=8 (nw) ----
        float acc[6][4];
#pragma unroll
        for (int g = 0; g < 6; g++)
#pragma unroll
            for (int k = 0; k < 4; k++) acc[g][k] = 0.0f;

        const u32 abase = sbase + (u32)(p * BUF_BYTES);
        const int rl = lane & 15;
        const int rlo = rl & 7;
        const int rr = mt * 16 + rl;
#pragma unroll
        for (int kt = 0; kt < 4; kt++) {
            const int cb = (kt * 2 + (lane >> 4)) ^ rlo;
            const u32 aoff = abase + (u32)(rr * 128 + cb * 16);
            u32 ah[4], al[4];
            // s1 -> Wss (acc0) and Wsv (acc2)
            ldsm4(ah, aoff + 0 * MAT_BYTES);
            ldsm4(al, aoff + 1 * MAT_BYTES);
            mma16816(acc[0], ah, Bh[0][kt]);
            mma16816(acc[0], al, Bh[0][kt]);
            mma16816(acc[0], ah, Bl[0][kt]);
            mma16816(acc[2], ah, Bh[2][kt]);
            mma16816(acc[2], al, Bh[2][kt]);
            mma16816(acc[2], ah, Bl[2][kt]);
            // b -> Wvv (acc1)
            ldsm4(ah, aoff + 2 * MAT_BYTES);
            ldsm4(al, aoff + 3 * MAT_BYTES);
            mma16816(acc[1], ah, Bh[1][kt]);
            mma16816(acc[1], al, Bh[1][kt]);
            mma16816(acc[1], ah, Bl[1][kt]);
            // vx,vy,vz -> Wvs (acc3..5)
#pragma unroll
            for (int i = 0; i < 3; i++) {
                ldsm4(ah, aoff + (4 + 2 * i) * MAT_BYTES);
                ldsm4(al, aoff + (5 + 2 * i) * MAT_BYTES);
                mma16816(acc[3 + i], ah, Bh[3][kt]);
                mma16816(acc[3 + i], al, Bh[3][kt]);
                mma16816(acc[3 + i], ah, Bl[3][kt]);
            }
        }

        // ---- epilogue ----
        const float4* sin2 = (const float4*)(smem + p * BUF_BYTES + 10 * MAT_BYTES);
        const int row0 = c * RPC;
        const int wc = nw * 8 + (lane & 3) * 2;
#pragma unroll
        for (int h = 0; h < 2; h++) {
            const int rloc = mt * 16 + (lane >> 2) + h * 8;
            const int row = row0 + rloc;
            if (row >= n) continue;
            const float4 q = sin2[rloc];
            float* o = out + (size_t)row * 256;
            const int ci = h * 2;
            const float s0  = q.x * acc[0][ci]     + acc[1][ci]     + bias2.x;
            const float s1v = q.x * acc[0][ci + 1] + acc[1][ci + 1] + bias2.y;
            *(float2*)(o + wc) = make_float2(s0, s1v);

            float vv6[6];
#pragma unroll
            for (int j = 0; j < 2; j++) {
                const float p3 = acc[2][ci + j];
                vv6[3 * j]     = p3 * q.y + acc[3][ci + j] * q.x;
                vv6[3 * j + 1] = p3 * q.z + acc[4][ci + j] * q.x;
                vv6[3 * j + 2] = p3 * q.w + acc[5][ci + j] * q.x;
            }
            float* ov = o + 64 + 3 * wc;
            *(float2*)(ov)     = make_float2(vv6[0], vv6[1]);
            *(float2*)(ov + 2) = make_float2(vv6[2], vv6[3]);
            *(float2*)(ov + 4) = make_float2(vv6[4], vv6[5]);
        }
        __syncthreads();
        p ^= 1;
    }
}

extern "C" void kernel_launch(void* const* d_in, const int* in_sizes, int n_in,
                              void* d_out, int out_size)
{
    const float* in1  = (const float*)d_in[0];
    const float* in2  = (const float*)d_in[1];
    const float* Wss  = (const float*)d_in[2];
    const float* Wvv  = (const float*)d_in[3];
    const float* Wsv  = (const float*)d_in[4];
    const float* Wvs  = (const float*)d_in[5];
    const float* bias = (const float*)d_in[6];
    float* out = (float*)d_out;

    const int n = in_sizes[0] / 256;

    cudaFuncSetAttribute(o3tp_mma_kernel, cudaFuncAttributeMaxDynamicSharedMemorySize, SMEM_BYTES);

    int dev = 0, sms = 148;
    cudaGetDevice(&dev);
    cudaDeviceGetAttribute(&sms, cudaDevAttrMultiProcessorCount, dev);

    o3tp_mma_kernel<<<sms, THREADS, SMEM_BYTES>>>(in1, in2, Wss, Wvv, Wsv, Wvs, bias, out, n);
}

// round 8
// speedup vs baseline: 1.1060x; 1.0778x over previous
#include <cuda_runtime.h>
#include <cuda_bf16.h>
#include <cstdint>
#include <cstddef>

// O3 tensor product, MUL=64, via mma.sync bf16 (hi/lo split, fp32 accum).
//   Q1 = s1 @ Wss ; Q2 = b @ Wvv ; P3 = s1 @ Wsv ; P4i = v1_i @ Wvs
//   out_s       = s2*Q1 + Q2 + bias
//   out_v[w][i] = P3[w]*v2_i + P4i[w]*s2
// (all reference scale factors cancel; b = dot(v1,v2)/sqrt(3))
//
// R8: register-level software pipeline — next chunk's LDGs issue BEFORE the
// MMA phase, pack+STS happens AFTER (covers DRAM latency with tensor work).

#define THREADS 512
#define RPC 32                      // rows per chunk
#define MAT_BYTES (RPC * 128)       // one staged A matrix: 32 rows x 128B (64 bf16)
#define BUF_BYTES (10 * MAT_BYTES + 512)
#define SMEM_BYTES (2 * BUF_BYTES)

typedef unsigned int u32;

__device__ __forceinline__ u32 smem_u32(const void* p) {
    u32 a; asm("{ .reg .u64 t; cvta.to.shared.u64 t, %1; cvt.u32.u64 %0, t; }" : "=r"(a) : "l"(p));
    return a;
}

__device__ __forceinline__ void ldsm4(u32* d, u32 addr) {
    asm volatile("ldmatrix.sync.aligned.m8n8.x4.shared.b16 {%0,%1,%2,%3}, [%4];"
                 : "=r"(d[0]), "=r"(d[1]), "=r"(d[2]), "=r"(d[3]) : "r"(addr));
}

__device__ __forceinline__ void mma16816(float* c, const u32* a, const u32* b) {
    asm volatile("mma.sync.aligned.m16n8k16.row.col.f32.bf16.bf16.f32 "
                 "{%0,%1,%2,%3},{%4,%5,%6,%7},{%8,%9},{%0,%1,%2,%3};"
                 : "+f"(c[0]), "+f"(c[1]), "+f"(c[2]), "+f"(c[3])
                 : "r"(a[0]), "r"(a[1]), "r"(a[2]), "r"(a[3]), "r"(b[0]), "r"(b[1]));
}

// split two floats into packed bf16x2 hi and lo (lo = residual)
__device__ __forceinline__ void split2(float x0, float x1, u32& hi, u32& lo) {
    __nv_bfloat162 h = __floats2bfloat162_rn(x0, x1);
    float r0 = x0 - __bfloat162float(h.x);
    float r1 = x1 - __bfloat162float(h.y);
    __nv_bfloat162 l = __floats2bfloat162_rn(r0, r1);
    hi = *(u32*)&h; lo = *(u32*)&l;
}

// pack 4 floats -> hi uint2 + lo uint2 (bf16)
__device__ __forceinline__ void pack4(const float* x, uint2& hi, uint2& lo) {
    u32 h0, h1, l0, l1;
    split2(x[0], x[1], h0, l0);
    split2(x[2], x[3], h1, l1);
    hi = make_uint2(h0, h1);
    lo = make_uint2(l0, l1);
}

// Per-thread staged registers for one chunk work-item:
// r = t>>4 (row 0..31), g4 = t&15 (u-group of 4: u = 4g4..4g4+3)
struct ChunkRegs {
    float4 s1a;    // s1[4g4..4g4+3]
    float4 v0, v1, v2;  // 12 floats: v1[u][xyz]
    float4 q;      // s2, v2x, v2y, v2z
};

__device__ __forceinline__ void chunk_load(ChunkRegs& cr, const float* __restrict__ in1,
                                           const float* __restrict__ in2,
                                           int row0, int n, int t)
{
    const int r = t >> 4, g4 = t & 15;
    int row = row0 + r; if (row >= n) row = n - 1;
    const float4* p1 = (const float4*)(in1 + (size_t)row * 256);
    cr.s1a = p1[g4];
    cr.v0  = p1[16 + 3 * g4];
    cr.v1  = p1[16 + 3 * g4 + 1];
    cr.v2  = p1[16 + 3 * g4 + 2];
    cr.q   = *(const float4*)(in2 + (size_t)row * 4);
}

// A-matrix order in staging: 0 s1h 1 s1l 2 bh 3 bl 4 xh 5 xl 6 yh 7 yl 8 zh 9 zl
__device__ __forceinline__ void chunk_store(char* buf, const ChunkRegs& cr, int t)
{
    const int r = t >> 4, g4 = t & 15;
    if (g4 == 0) *(float4*)(buf + 10 * MAT_BYTES + r * 16) = cr.q;

    const float s1[4] = { cr.s1a.x, cr.s1a.y, cr.s1a.z, cr.s1a.w };
    const float vv[12] = { cr.v0.x, cr.v0.y, cr.v0.z, cr.v0.w,
                           cr.v1.x, cr.v1.y, cr.v1.z, cr.v1.w,
                           cr.v2.x, cr.v2.y, cr.v2.z, cr.v2.w };
    const float INV_SQRT3 = 0.57735026918962576451f;
    float bb[4], vx[4], vy[4], vz[4];
#pragma unroll
    for (int j = 0; j < 4; j++) {
        vx[j] = vv[3 * j]; vy[j] = vv[3 * j + 1]; vz[j] = vv[3 * j + 2];
        bb[j] = (vx[j] * cr.q.y + vy[j] * cr.q.z + vz[j] * cr.q.w) * INV_SQRT3;
    }

    // swizzled 8B offset: 16B block = g4>>1, XOR with row&7, sub-8B = g4&1
    const u32 off = (u32)(r * 128 + (((g4 >> 1) ^ (r & 7)) << 4) + (g4 & 1) * 8);
    uint2 hi, lo;
    pack4(s1, hi, lo);
    *(uint2*)(buf + 0 * MAT_BYTES + off) = hi; *(uint2*)(buf + 1 * MAT_BYTES + off) = lo;
    pack4(bb, hi, lo);
    *(uint2*)(buf + 2 * MAT_BYTES + off) = hi; *(uint2*)(buf + 3 * MAT_BYTES + off) = lo;
    pack4(vx, hi, lo);
    *(uint2*)(buf + 4 * MAT_BYTES + off) = hi; *(uint2*)(buf + 5 * MAT_BYTES + off) = lo;
    pack4(vy, hi, lo);
    *(uint2*)(buf + 6 * MAT_BYTES + off) = hi; *(uint2*)(buf + 7 * MAT_BYTES + off) = lo;
    pack4(vz, hi, lo);
    *(uint2*)(buf + 8 * MAT_BYTES + off) = hi; *(uint2*)(buf + 9 * MAT_BYTES + off) = lo;
}

__global__ void __launch_bounds__(THREADS, 1)
o3tp_mma_kernel(const float* __restrict__ in1, const float* __restrict__ in2,
                const float* __restrict__ Wss, const float* __restrict__ Wvv,
                const float* __restrict__ Wsv, const float* __restrict__ Wvs,
                const float* __restrict__ bias, float* __restrict__ out, int n)
{
    extern __shared__ char smem[];
    const u32 sbase = smem_u32(smem);
    const int t = threadIdx.x, wid = t >> 5, lane = t & 31;
    const int nw = wid & 7;         // n-slice: cols nw*8..nw*8+7
    const int mt = wid >> 3;        // m-half: rows mt*16..mt*16+15

    // ---- persistent B fragments: warp's n-slice (8 cols) of all 4 matrices ----
    u32 Bh[4][4][2], Bl[4][4][2];
    {
        const int wcol = nw * 8 + (lane >> 2);
        const float* Ws[4] = { Wss, Wvv, Wsv, Wvs };
#pragma unroll
        for (int m = 0; m < 4; m++)
#pragma unroll
            for (int kt = 0; kt < 4; kt++)
#pragma unroll
                for (int b2 = 0; b2 < 2; b2++) {
                    const int u = kt * 16 + (lane & 3) * 2 + b2 * 8;
                    const float w0 = __ldg(Ws[m] + u * 64 + wcol);
                    const float w1 = __ldg(Ws[m] + (u + 1) * 64 + wcol);
                    split2(w0, w1, Bh[m][kt][b2], Bl[m][kt][b2]);
                }
    }
    float2 bias2;
    {
        const int w0 = nw * 8 + (lane & 3) * 2;
        bias2 = make_float2(__ldg(bias + w0), __ldg(bias + w0 + 1));
    }

    const int nch = (n + RPC - 1) / RPC;
    int c = blockIdx.x;
    ChunkRegs cr;
    if (c < nch) {
        chunk_load(cr, in1, in2, c * RPC, n, t);
        chunk_store(smem, cr, t);
    }
    __syncthreads();

    int p = 0;
    for (; c < nch; c += gridDim.x) {
        const int cn = c + gridDim.x;
        const bool have_next = cn < nch;
        // issue next chunk's global loads FIRST (latency covered by MMA below)
        if (have_next) chunk_load(cr, in1, in2, cn * RPC, n, t);

        // ---- MMA phase on buffer p: warp computes M=16 (m-half mt), N=8 (nw) ----
        float acc[6][4];
#pragma unroll
        for (int g = 0; g < 6; g++)
#pragma unroll
            for (int k = 0; k < 4; k++) acc[g][k] = 0.0f;

        const u32 abase = sbase + (u32)(p * BUF_BYTES);
        const int rl = lane & 15;
        const int rlo = rl & 7;
        const int rr = mt * 16 + rl;
#pragma unroll
        for (int kt = 0; kt < 4; kt++) {
            const int cb = (kt * 2 + (lane >> 4)) ^ rlo;
            const u32 aoff = abase + (u32)(rr * 128 + cb * 16);
            u32 ah[4], al[4];
            // s1 -> Wss (acc0) and Wsv (acc2)
            ldsm4(ah, aoff + 0 * MAT_BYTES);
            ldsm4(al, aoff + 1 * MAT_BYTES);
            mma16816(acc[0], ah, Bh[0][kt]);
            mma16816(acc[0], al, Bh[0][kt]);
            mma16816(acc[0], ah, Bl[0][kt]);
            mma16816(acc[2], ah, Bh[2][kt]);
            mma16816(acc[2], al, Bh[2][kt]);
            mma16816(acc[2], ah, Bl[2][kt]);
            // b -> Wvv (acc1)
            ldsm4(ah, aoff + 2 * MAT_BYTES);
            ldsm4(al, aoff + 3 * MAT_BYTES);
            mma16816(acc[1], ah, Bh[1][kt]);
            mma16816(acc[1], al, Bh[1][kt]);
            mma16816(acc[1], ah, Bl[1][kt]);
            // vx,vy,vz -> Wvs (acc3..5)
#pragma unroll
            for (int i = 0; i < 3; i++) {
                ldsm4(ah, aoff + (4 + 2 * i) * MAT_BYTES);
                ldsm4(al, aoff + (5 + 2 * i) * MAT_BYTES);
                mma16816(acc[3 + i], ah, Bh[3][kt]);
                mma16816(acc[3 + i], al, Bh[3][kt]);
                mma16816(acc[3 + i], ah, Bl[3][kt]);
            }
        }

        // ---- epilogue (independent of pending loads) ----
        const float4* sin2 = (const float4*)(smem + p * BUF_BYTES + 10 * MAT_BYTES);
        const int row0 = c * RPC;
        const int wc = nw * 8 + (lane & 3) * 2;
#pragma unroll
        for (int h = 0; h < 2; h++) {
            const int rloc = mt * 16 + (lane >> 2) + h * 8;
            const int row = row0 + rloc;
            if (row >= n) continue;
            const float4 q = sin2[rloc];
            float* o = out + (size_t)row * 256;
            const int ci = h * 2;
            const float s0  = q.x * acc[0][ci]     + acc[1][ci]     + bias2.x;
            const float s1v = q.x * acc[0][ci + 1] + acc[1][ci + 1] + bias2.y;
            *(float2*)(o + wc) = make_float2(s0, s1v);

            float vv6[6];
#pragma unroll
            for (int j = 0; j < 2; j++) {
                const float p3 = acc[2][ci + j];
                vv6[3 * j]     = p3 * q.y + acc[3][ci + j] * q.x;
                vv6[3 * j + 1] = p3 * q.z + acc[4][ci + j] * q.x;
                vv6[3 * j + 2] = p3 * q.w + acc[5][ci + j] * q.x;
            }
            float* ov = o + 64 + 3 * wc;
            *(float2*)(ov)     = make_float2(vv6[0], vv6[1]);
            *(float2*)(ov + 2) = make_float2(vv6[2], vv6[3]);
            *(float2*)(ov + 4) = make_float2(vv6[4], vv6[5]);
        }

        // ---- pack + store next chunk (loads have landed by now) ----
        if (have_next) chunk_store(smem + (p ^ 1) * BUF_BYTES, cr, t);

        __syncthreads();
        p ^= 1;
    }
}

extern "C" void kernel_launch(void* const* d_in, const int* in_sizes, int n_in,
                              void* d_out, int out_size)
{
    const float* in1  = (const float*)d_in[0];
    const float* in2  = (const float*)d_in[1];
    const float* Wss  = (const float*)d_in[2];
    const float* Wvv  = (const float*)d_in[3];
    const float* Wsv  = (const float*)d_in[4];
    const float* Wvs  = (const float*)d_in[5];
    const float* bias = (const float*)d_in[6];
    float* out = (float*)d_out;

    const int n = in_sizes[0] / 256;

    cudaFuncSetAttribute(o3tp_mma_kernel, cudaFuncAttributeMaxDynamicSharedMemorySize, SMEM_BYTES);

    int dev = 0, sms = 148;
    cudaGetDevice(&dev);
    cudaDeviceGetAttribute(&sms, cudaDevAttrMultiProcessorCount, dev);

    o3tp_mma_kernel<<<sms, THREADS, SMEM_BYTES>>>(in1, in2, Wss, Wvv, Wsv, Wvs, bias, out, n);
}